// round 6
// baseline (speedup 1.0000x reference)
#include <cuda_runtime.h>
#include <math.h>
#include <stdint.h>

// ---------------- problem constants ----------------
#define NBATCH   2
#define SEQLEN   512
#define D_INNER  4096
#define D_STATE  16
#define DT_RANK  128
#define NROWS    (NBATCH * SEQLEN)          // 1024
#define XPC      (DT_RANK + 2 * D_STATE)    // 160
#define KSPLIT   16

// ---------------- scratch ----------------
__device__ float g_part[KSPLIT * NROWS * XPC];   // 10.5 MB
__device__ float g_xp[NROWS * XPC];
__device__ float g_dt[NROWS * D_INNER];

// ---------------- helpers ----------------
__device__ __forceinline__ float ex2f(float v) {
    float r; asm("ex2.approx.ftz.f32 %0, %1;" : "=f"(r) : "f"(v)); return r;
}
__device__ __forceinline__ float softplusf(float z) {
    return fmaxf(z, 0.0f) + log1pf(__expf(-fabsf(z)));
}
__device__ __forceinline__ void cp16(float* dst, const float* src) {
    unsigned s = (unsigned)__cvta_generic_to_shared(dst);
    asm volatile("cp.async.cg.shared.global [%0], [%1], 16;" :: "r"(s), "l"(src));
}
__device__ __forceinline__ void cp_commit() { asm volatile("cp.async.commit_group;"); }
template <int N>
__device__ __forceinline__ void cp_wait() { asm volatile("cp.async.wait_group %0;" :: "n"(N)); }

// =====================================================================
// GEMM1: part[z][row][c] = sum_{k in slice z} x[row][k] * w[c][k]
// grid (8 Mtiles of 128, 2 Ntiles of 80, 16 ksplits), 256 thr.
// smem k-major, double-buffered cp.async. micro-tile 8x5. KC=16.
// =====================================================================
#define G1_KC 16
#define G1_CHUNKS 16    // Kslice 256 = 16 * 16

__global__ __launch_bounds__(256, 1)
void gemm1_kernel(const float* __restrict__ x, const float* __restrict__ w)
{
    __shared__ float As[2][G1_KC][132];   // [buf][k][row 0..127 +4 pad]
    __shared__ float Bs[2][G1_KC][84];    // [buf][k][col 0..79  +4 pad]

    const int tid = threadIdx.x;
    const int m0 = blockIdx.x * 128;
    const int n0 = blockIdx.y * 80;
    const int k0 = blockIdx.z * 256;

    const int ty = tid >> 4, tx = tid & 15;
    const int r0 = ty * 8, c0 = tx * 5;

    // loaders: q = k-quad (0..3), r/col = row index
    const int lq = tid & 3;
    const int lr = tid >> 2;              // 0..63

    const float* xg0 = x + (size_t)(m0 + lr) * D_INNER + k0 + lq * 4;
    const float* xg1 = x + (size_t)(m0 + 64 + lr) * D_INNER + k0 + lq * 4;
    const float* wg0 = w + (size_t)(n0 + lr) * D_INNER + k0 + lq * 4;
    const float* wg1 = w + (size_t)(n0 + 64 + lr) * D_INNER + k0 + lq * 4; // tid<64

    auto load_chunk = [&](int c, int buf) {
        const int koff = c * G1_KC;
        cp16(&As[buf][lq * 4][lr],      xg0 + koff);
        cp16(&As[buf][lq * 4][64 + lr], xg1 + koff);
        cp16(&Bs[buf][lq * 4][lr],      wg0 + koff);
        if (tid < 64)
            cp16(&Bs[buf][lq * 4][64 + lr], wg1 + koff);
    };
    // NOTE: cp16 writes 16B along the row dim?? No — it writes 16 contiguous
    // bytes of SMEM, but we need a transpose (global k-contiguous -> smem
    // k-major). cp.async cannot transpose, so stage through registers instead.
    (void)load_chunk;

    float acc[8][5];
#pragma unroll
    for (int i = 0; i < 8; i++)
#pragma unroll
        for (int j = 0; j < 5; j++) acc[i][j] = 0.0f;

    // register-prefetch pipeline (transposing store)
    float4 pa0 = *(const float4*)xg0;
    float4 pa1 = *(const float4*)xg1;
    float4 pb0 = *(const float4*)wg0;
    float4 pb1 = make_float4(0, 0, 0, 0);
    if (tid < 64) pb1 = *(const float4*)wg1;

    for (int c = 0; c < G1_CHUNKS; c++) {
        const int buf = c & 1;
        As[buf][lq * 4 + 0][lr] = pa0.x; As[buf][lq * 4 + 1][lr] = pa0.y;
        As[buf][lq * 4 + 2][lr] = pa0.z; As[buf][lq * 4 + 3][lr] = pa0.w;
        As[buf][lq * 4 + 0][64 + lr] = pa1.x; As[buf][lq * 4 + 1][64 + lr] = pa1.y;
        As[buf][lq * 4 + 2][64 + lr] = pa1.z; As[buf][lq * 4 + 3][64 + lr] = pa1.w;
        Bs[buf][lq * 4 + 0][lr] = pb0.x; Bs[buf][lq * 4 + 1][lr] = pb0.y;
        Bs[buf][lq * 4 + 2][lr] = pb0.z; Bs[buf][lq * 4 + 3][lr] = pb0.w;
        if (tid < 64) {
            Bs[buf][lq * 4 + 0][64 + lr] = pb1.x; Bs[buf][lq * 4 + 1][64 + lr] = pb1.y;
            Bs[buf][lq * 4 + 2][64 + lr] = pb1.z; Bs[buf][lq * 4 + 3][64 + lr] = pb1.w;
        }
        __syncthreads();

        if (c + 1 < G1_CHUNKS) {
            const int koff = (c + 1) * G1_KC;
            pa0 = *(const float4*)(xg0 + koff);
            pa1 = *(const float4*)(xg1 + koff);
            pb0 = *(const float4*)(wg0 + koff);
            if (tid < 64) pb1 = *(const float4*)(wg1 + koff);
        }

#pragma unroll
        for (int k = 0; k < G1_KC; k++) {
            float4 a01 = *(const float4*)&As[buf][k][r0];
            float4 a23 = *(const float4*)&As[buf][k][r0 + 4];
            float a[8] = {a01.x, a01.y, a01.z, a01.w, a23.x, a23.y, a23.z, a23.w};
            float b[5];
#pragma unroll
            for (int j = 0; j < 5; j++) b[j] = Bs[buf][k][c0 + j];
#pragma unroll
            for (int i = 0; i < 8; i++)
#pragma unroll
                for (int j = 0; j < 5; j++)
                    acc[i][j] = fmaf(a[i], b[j], acc[i][j]);
        }
        __syncthreads();
    }

    float* outp = g_part + ((size_t)blockIdx.z * NROWS + m0 + r0) * XPC + n0 + c0;
#pragma unroll
    for (int i = 0; i < 8; i++)
#pragma unroll
        for (int j = 0; j < 5; j++)
            outp[(size_t)i * XPC + j] = acc[i][j];
}

// =====================================================================
// reduce split-K (float4)
// =====================================================================
__global__ void reduce_kernel()
{
    int i = blockIdx.x * blockDim.x + threadIdx.x;
    const int n4 = NROWS * XPC / 4;
    if (i < n4) {
        const float4* p = (const float4*)g_part;
        float4 s = p[i];
#pragma unroll
        for (int z = 1; z < KSPLIT; z++) {
            float4 v = p[(size_t)z * n4 + i];
            s.x += v.x; s.y += v.y; s.z += v.z; s.w += v.w;
        }
        ((float4*)g_xp)[i] = s;
    }
}

// =====================================================================
// GEMM2: g_dt[row][d] = softplus( sum_r xp[row][r]*dtw[d][r] + b[d] )
// grid (8 Mtiles of 128, 32 Ntiles of 128), 256 thr.
// smem k-major, micro-tile 8x8, KC=16, 8 chunks.
// =====================================================================
#define G2_KC 16
#define G2_CHUNKS 8

__global__ __launch_bounds__(256, 1)
void gemm2_kernel(const float* __restrict__ dtw, const float* __restrict__ dtb)
{
    __shared__ float As[2][G2_KC][132];
    __shared__ float Bs[2][G2_KC][132];

    const int tid = threadIdx.x;
    const int m0 = blockIdx.x * 128;
    const int n0 = blockIdx.y * 128;
    const int ty = tid >> 4, tx = tid & 15;
    const int r0 = ty * 8, c0 = tx * 8;

    const int lq = tid & 3;
    const int lr = tid >> 2;

    const float* ag0 = g_xp + (size_t)(m0 + lr) * XPC + lq * 4;
    const float* ag1 = g_xp + (size_t)(m0 + 64 + lr) * XPC + lq * 4;
    const float* bg0 = dtw + (size_t)(n0 + lr) * DT_RANK + lq * 4;
    const float* bg1 = dtw + (size_t)(n0 + 64 + lr) * DT_RANK + lq * 4;

    float acc[8][8];
#pragma unroll
    for (int i = 0; i < 8; i++)
#pragma unroll
        for (int j = 0; j < 8; j++) acc[i][j] = 0.0f;

    float4 pa0 = *(const float4*)ag0;
    float4 pa1 = *(const float4*)ag1;
    float4 pb0 = *(const float4*)bg0;
    float4 pb1 = *(const float4*)bg1;

    for (int c = 0; c < G2_CHUNKS; c++) {
        const int buf = c & 1;
        As[buf][lq * 4 + 0][lr] = pa0.x; As[buf][lq * 4 + 1][lr] = pa0.y;
        As[buf][lq * 4 + 2][lr] = pa0.z; As[buf][lq * 4 + 3][lr] = pa0.w;
        As[buf][lq * 4 + 0][64 + lr] = pa1.x; As[buf][lq * 4 + 1][64 + lr] = pa1.y;
        As[buf][lq * 4 + 2][64 + lr] = pa1.z; As[buf][lq * 4 + 3][64 + lr] = pa1.w;
        Bs[buf][lq * 4 + 0][lr] = pb0.x; Bs[buf][lq * 4 + 1][lr] = pb0.y;
        Bs[buf][lq * 4 + 2][lr] = pb0.z; Bs[buf][lq * 4 + 3][lr] = pb0.w;
        Bs[buf][lq * 4 + 0][64 + lr] = pb1.x; Bs[buf][lq * 4 + 1][64 + lr] = pb1.y;
        Bs[buf][lq * 4 + 2][64 + lr] = pb1.z; Bs[buf][lq * 4 + 3][64 + lr] = pb1.w;
        __syncthreads();

        if (c + 1 < G2_CHUNKS) {
            const int koff = (c + 1) * G2_KC;
            pa0 = *(const float4*)(ag0 + koff);
            pa1 = *(const float4*)(ag1 + koff);
            pb0 = *(const float4*)(bg0 + koff);
            pb1 = *(const float4*)(bg1 + koff);
        }

#pragma unroll
        for (int k = 0; k < G2_KC; k++) {
            float4 a01 = *(const float4*)&As[buf][k][r0];
            float4 a23 = *(const float4*)&As[buf][k][r0 + 4];
            float4 b01 = *(const float4*)&Bs[buf][k][c0];
            float4 b23 = *(const float4*)&Bs[buf][k][c0 + 4];
            float a[8] = {a01.x, a01.y, a01.z, a01.w, a23.x, a23.y, a23.z, a23.w};
            float b[8] = {b01.x, b01.y, b01.z, b01.w, b23.x, b23.y, b23.z, b23.w};
#pragma unroll
            for (int i = 0; i < 8; i++)
#pragma unroll
                for (int j = 0; j < 8; j++)
                    acc[i][j] = fmaf(a[i], b[j], acc[i][j]);
        }
        __syncthreads();
    }

    float bias[8];
#pragma unroll
    for (int j = 0; j < 8; j++) bias[j] = dtb[n0 + c0 + j];

#pragma unroll
    for (int i = 0; i < 8; i++) {
        float o[8];
#pragma unroll
        for (int j = 0; j < 8; j++) o[j] = softplusf(acc[i][j] + bias[j]);
        float* op = &g_dt[(size_t)(m0 + r0 + i) * D_INNER + n0 + c0];
        *(float4*)op = make_float4(o[0], o[1], o[2], o[3]);
        *(float4*)(op + 4) = make_float4(o[4], o[5], o[6], o[7]);
    }
}

// =====================================================================
// Scan (R3 layout): 256 blocks (2 batches x 128 d-tiles of 32 channels),
// 128 thr, 4 lanes/channel, 4 states/lane, cp.async double-buffered.
// =====================================================================
#define LT 64
#define NTILES (SEQLEN / LT)

__global__ __launch_bounds__(128, 4)
void scan_kernel(const float* __restrict__ x, const float* __restrict__ A_log,
                 const float* __restrict__ Dp, float* __restrict__ y)
{
    extern __shared__ float sm[];
    float* xs  = sm;                   // [2][LT][32]
    float* dts = xs + 2 * LT * 32;     // [2][LT][32]
    float* Bsm = dts + 2 * LT * 32;    // [2][LT][16]
    float* Csm = Bsm + 2 * LT * 16;    // [2][LT][16]

    const int tid = threadIdx.x;
    const int b   = blockIdx.x >> 7;
    const int d0  = (blockIdx.x & 127) * 32;
    const int lane = tid & 31;
    const int w    = tid >> 5;
    const int q    = lane & 3;
    const int cl   = w * 8 + (lane >> 2);
    const int d    = d0 + cl;

    float A2[4];
#pragma unroll
    for (int j = 0; j < 4; j++)
        A2[j] = -__expf(A_log[d * D_STATE + q * 4 + j]) * 1.4426950408889634f;
    const float Dd = Dp[d];

    float h0 = 0.f, h1 = 0.f, h2 = 0.f, h3 = 0.f;

    const float* xg  = x    + (size_t)b * SEQLEN * D_INNER + d0;
    const float* dtg = g_dt + (size_t)b * SEQLEN * D_INNER + d0;
    const float* Bg  = g_xp + (size_t)b * SEQLEN * XPC + DT_RANK;
    const float* Cg  = g_xp + (size_t)b * SEQLEN * XPC + DT_RANK + D_STATE;

    auto load_tile = [&](int t, int buf) {
        const int l0 = t * LT;
        for (int i = tid; i < LT * 8; i += 128) {
            int ll = i >> 3, sg = (i & 7) * 4;
            cp16(&xs [(buf * LT + ll) * 32 + sg], xg  + (size_t)(l0 + ll) * D_INNER + sg);
            cp16(&dts[(buf * LT + ll) * 32 + sg], dtg + (size_t)(l0 + ll) * D_INNER + sg);
        }
        for (int i = tid; i < LT * 4; i += 128) {
            int ll = i >> 2, sg = (i & 3) * 4;
            cp16(&Bsm[(buf * LT + ll) * 16 + sg], Bg + (size_t)(l0 + ll) * XPC + sg);
            cp16(&Csm[(buf * LT + ll) * 16 + sg], Cg + (size_t)(l0 + ll) * XPC + sg);
        }
    };

    load_tile(0, 0);
    cp_commit();

    for (int t = 0; t < NTILES; t++) {
        if (t + 1 < NTILES) {
            load_tile(t + 1, (t + 1) & 1);
            cp_commit();
            cp_wait<1>();
        } else {
            cp_wait<0>();
        }
        __syncthreads();

        const int buf = t & 1;
        const float* xsb  = &xs [buf * LT * 32];
        const float* dtb_ = &dts[buf * LT * 32];
        const float* Bb   = &Bsm[buf * LT * 16];
        const float* Cb   = &Csm[buf * LT * 16];

        float* yout = y + ((size_t)b * SEQLEN + t * LT) * D_INNER + d;

#pragma unroll 4
        for (int ll = 0; ll < LT; ll++) {
            float dtv = dtb_[ll * 32 + cl];
            float xv  = xsb [ll * 32 + cl];
            float4 Bv = *(const float4*)&Bb[ll * 16 + q * 4];
            float4 Cv = *(const float4*)&Cb[ll * 16 + q * 4];

            float dtx = dtv * xv;
            float e0 = ex2f(dtv * A2[0]);
            float e1 = ex2f(dtv * A2[1]);
            float e2 = ex2f(dtv * A2[2]);
            float e3 = ex2f(dtv * A2[3]);
            h0 = fmaf(e0, h0, dtx * Bv.x);
            h1 = fmaf(e1, h1, dtx * Bv.y);
            h2 = fmaf(e2, h2, dtx * Bv.z);
            h3 = fmaf(e3, h3, dtx * Bv.w);

            float p = h0 * Cv.x;
            p = fmaf(h1, Cv.y, p);
            p = fmaf(h2, Cv.z, p);
            p = fmaf(h3, Cv.w, p);
            p += __shfl_xor_sync(0xffffffffu, p, 1);
            p += __shfl_xor_sync(0xffffffffu, p, 2);

            if (q == 0) yout[(size_t)ll * D_INNER] = fmaf(Dd, xv, p);
        }
        __syncthreads();
    }
}

// =====================================================================
// launch
// =====================================================================
extern "C" void kernel_launch(void* const* d_in, const int* in_sizes, int n_in,
                              void* d_out, int out_size)
{
    const float* x     = (const float*)d_in[0];  // (2,512,4096)
    const float* A_log = (const float*)d_in[1];  // (4096,16)
    const float* Dp    = (const float*)d_in[2];  // (4096,)
    const float* xpw   = (const float*)d_in[3];  // (160,4096)
    const float* dtw   = (const float*)d_in[4];  // (4096,128)
    const float* dtb   = (const float*)d_in[5];  // (4096,)
    float* y = (float*)d_out;                    // (2,512,4096)

    gemm1_kernel<<<dim3(8, 2, KSPLIT), 256>>>(x, xpw);
    reduce_kernel<<<(NROWS * XPC / 4 + 255) / 256, 256>>>();
    gemm2_kernel<<<dim3(8, 32), 256>>>(dtw, dtb);
    scan_kernel<<<256, 128, 49152>>>(x, A_log, Dp, y);
}

// round 7
// speedup vs baseline: 1.4351x; 1.4351x over previous
#include <cuda_runtime.h>
#include <cuda_bf16.h>
#include <math.h>
#include <stdint.h>

// ---------------- problem constants ----------------
#define NBATCH   2
#define SEQLEN   512
#define D_INNER  4096
#define D_STATE  16
#define DT_RANK  128
#define NROWS    (NBATCH * SEQLEN)          // 1024
#define XPC      (DT_RANK + 2 * D_STATE)    // 160
#define KSPLIT   16

// ---------------- scratch ----------------
__device__ float g_part[KSPLIT * NROWS * XPC];
__device__ float g_xp[NROWS * XPC];
__device__ float g_dt[NROWS * D_INNER];

// ---------------- helpers ----------------
__device__ __forceinline__ float ex2f(float v) {
    float r; asm("ex2.approx.ftz.f32 %0, %1;" : "=f"(r) : "f"(v)); return r;
}
__device__ __forceinline__ float softplusf(float z) {
    return fmaxf(z, 0.0f) + log1pf(__expf(-fabsf(z)));
}
__device__ __forceinline__ void cp16(float* dst, const float* src) {
    unsigned s = (unsigned)__cvta_generic_to_shared(dst);
    asm volatile("cp.async.cg.shared.global [%0], [%1], 16;" :: "r"(s), "l"(src));
}
__device__ __forceinline__ void cp_commit() { asm volatile("cp.async.commit_group;"); }
template <int N>
__device__ __forceinline__ void cp_wait() { asm volatile("cp.async.wait_group %0;" :: "n"(N)); }

// split a pair of fp32 into packed bf16 hi and lo (residual) words
__device__ __forceinline__ void split2(float x, float y, uint32_t& hi, uint32_t& lo) {
    __nv_bfloat16 hx = __float2bfloat16(x);
    __nv_bfloat16 hy = __float2bfloat16(y);
    float rx = x - __bfloat162float(hx);
    float ry = y - __bfloat162float(hy);
    __nv_bfloat162 H; H.x = hx; H.y = hy;
    __nv_bfloat162 L = __floats2bfloat162_rn(rx, ry);
    hi = *reinterpret_cast<uint32_t*>(&H);
    lo = *reinterpret_cast<uint32_t*>(&L);
}

__device__ __forceinline__ void mma16816(float c[4],
    uint32_t a0, uint32_t a1, uint32_t a2, uint32_t a3, uint32_t b0, uint32_t b1)
{
    asm volatile(
        "mma.sync.aligned.m16n8k16.row.col.f32.bf16.bf16.f32 "
        "{%0,%1,%2,%3}, {%4,%5,%6,%7}, {%8,%9}, {%0,%1,%2,%3};"
        : "+f"(c[0]), "+f"(c[1]), "+f"(c[2]), "+f"(c[3])
        : "r"(a0), "r"(a1), "r"(a2), "r"(a3), "r"(b0), "r"(b1));
}

__device__ __forceinline__ uint32_t ldu(const __nv_bfloat16* p) {
    return *reinterpret_cast<const uint32_t*>(p);
}

#define LDK 20   // bf16 smem row stride (16 data + 4 pad, even)

// =====================================================================
// GEMM1 (tensor): part[z][row][c] = sum_{k slice z} x[row][k]*w[c][k]
// grid (16 Mtiles of 64, 16 ksplits), 256 thr (8 warps: 2M x 4N).
// Kslice 256 = 16 chunks of k16, double-buffered. bf16 3-term split.
// =====================================================================
__global__ __launch_bounds__(256, 1)
void gemm1_kernel(const float* __restrict__ x, const float* __restrict__ w)
{
    __shared__ __nv_bfloat16 Ahi[2][64][LDK],  Alo[2][64][LDK];
    __shared__ __nv_bfloat16 Bhi[2][160][LDK], Blo[2][160][LDK];

    const int tid = threadIdx.x;
    const int m0 = blockIdx.x * 64;
    const int k0 = blockIdx.y * 256;

    const int lane = tid & 31, wid = tid >> 5;
    const int wm = (wid >> 2) * 32;        // 0 or 32
    const int wn = (wid & 3) * 40;         // 0,40,80,120
    const int g = lane >> 2, t2 = (lane & 3) * 2;

    // loaders
    const int arow = tid >> 2, akq = (tid & 3) * 4;           // A: 64x16
    const int br0 = tid >> 2,           bk0 = (tid & 3) * 4;  // B rows 0..63
    const int br1 = (tid + 256) >> 2,   bk1 = bk0;            // rows 64..127
    const int br2 = (tid + 512) >> 2,   bk2 = bk0;            // rows 128..159 (tid<128)
    const bool b2act = (tid < 128);

    const float* Ag = x + (size_t)(m0 + arow) * D_INNER + k0 + akq;
    const float* Bg0 = w + (size_t)br0 * D_INNER + k0 + bk0;
    const float* Bg1 = w + (size_t)br1 * D_INNER + k0 + bk1;
    const float* Bg2 = w + (size_t)br2 * D_INNER + k0 + bk2;

    float acc[2][5][4];
#pragma unroll
    for (int i = 0; i < 2; i++)
#pragma unroll
        for (int j = 0; j < 5; j++)
#pragma unroll
            for (int v = 0; v < 4; v++) acc[i][j][v] = 0.0f;

    float4 pa, pb0, pb1, pb2;
    auto ldregs = [&](int c) {
        const int ko = c * 16;
        pa  = *(const float4*)(Ag  + ko);
        pb0 = *(const float4*)(Bg0 + ko);
        pb1 = *(const float4*)(Bg1 + ko);
        if (b2act) pb2 = *(const float4*)(Bg2 + ko);
    };
    auto stregs = [&](int buf) {
        uint32_t h0, l0, h1, l1;
        split2(pa.x, pa.y, h0, l0); split2(pa.z, pa.w, h1, l1);
        *(uint32_t*)&Ahi[buf][arow][akq] = h0;     *(uint32_t*)&Ahi[buf][arow][akq + 2] = h1;
        *(uint32_t*)&Alo[buf][arow][akq] = l0;     *(uint32_t*)&Alo[buf][arow][akq + 2] = l1;
        split2(pb0.x, pb0.y, h0, l0); split2(pb0.z, pb0.w, h1, l1);
        *(uint32_t*)&Bhi[buf][br0][bk0] = h0;      *(uint32_t*)&Bhi[buf][br0][bk0 + 2] = h1;
        *(uint32_t*)&Blo[buf][br0][bk0] = l0;      *(uint32_t*)&Blo[buf][br0][bk0 + 2] = l1;
        split2(pb1.x, pb1.y, h0, l0); split2(pb1.z, pb1.w, h1, l1);
        *(uint32_t*)&Bhi[buf][br1][bk1] = h0;      *(uint32_t*)&Bhi[buf][br1][bk1 + 2] = h1;
        *(uint32_t*)&Blo[buf][br1][bk1] = l0;      *(uint32_t*)&Blo[buf][br1][bk1 + 2] = l1;
        if (b2act) {
            split2(pb2.x, pb2.y, h0, l0); split2(pb2.z, pb2.w, h1, l1);
            *(uint32_t*)&Bhi[buf][br2][bk2] = h0;  *(uint32_t*)&Bhi[buf][br2][bk2 + 2] = h1;
            *(uint32_t*)&Blo[buf][br2][bk2] = l0;  *(uint32_t*)&Blo[buf][br2][bk2 + 2] = l1;
        }
    };

    ldregs(0);
    stregs(0);

    for (int c = 0; c < 16; c++) {
        __syncthreads();
        const int buf = c & 1;
        if (c + 1 < 16) ldregs(c + 1);

        uint32_t ah[2][4], al[2][4];
#pragma unroll
        for (int mt = 0; mt < 2; mt++) {
            const int r = wm + mt * 16 + g;
            ah[mt][0] = ldu(&Ahi[buf][r][t2]);      ah[mt][1] = ldu(&Ahi[buf][r + 8][t2]);
            ah[mt][2] = ldu(&Ahi[buf][r][t2 + 8]);  ah[mt][3] = ldu(&Ahi[buf][r + 8][t2 + 8]);
            al[mt][0] = ldu(&Alo[buf][r][t2]);      al[mt][1] = ldu(&Alo[buf][r + 8][t2]);
            al[mt][2] = ldu(&Alo[buf][r][t2 + 8]);  al[mt][3] = ldu(&Alo[buf][r + 8][t2 + 8]);
        }
#pragma unroll
        for (int nt = 0; nt < 5; nt++) {
            const int n = wn + nt * 8 + g;
            uint32_t bh0 = ldu(&Bhi[buf][n][t2]), bh1 = ldu(&Bhi[buf][n][t2 + 8]);
            uint32_t bl0 = ldu(&Blo[buf][n][t2]), bl1 = ldu(&Blo[buf][n][t2 + 8]);
#pragma unroll
            for (int mt = 0; mt < 2; mt++) {
                mma16816(acc[mt][nt], ah[mt][0], ah[mt][1], ah[mt][2], ah[mt][3], bh0, bh1);
                mma16816(acc[mt][nt], ah[mt][0], ah[mt][1], ah[mt][2], ah[mt][3], bl0, bl1);
                mma16816(acc[mt][nt], al[mt][0], al[mt][1], al[mt][2], al[mt][3], bh0, bh1);
            }
        }
        if (c + 1 < 16) stregs((c + 1) & 1);
    }

    // epilogue -> g_part[z][row][col]
    float* outz = g_part + (size_t)blockIdx.y * NROWS * XPC;
#pragma unroll
    for (int mt = 0; mt < 2; mt++) {
        const int r = m0 + wm + mt * 16 + g;
#pragma unroll
        for (int nt = 0; nt < 5; nt++) {
            const int col = wn + nt * 8 + t2;
            *(float2*)&outz[(size_t)r * XPC + col]       = make_float2(acc[mt][nt][0], acc[mt][nt][1]);
            *(float2*)&outz[(size_t)(r + 8) * XPC + col] = make_float2(acc[mt][nt][2], acc[mt][nt][3]);
        }
    }
}

// =====================================================================
// reduce split-K (float4)
// =====================================================================
__global__ void reduce_kernel()
{
    int i = blockIdx.x * blockDim.x + threadIdx.x;
    const int n4 = NROWS * XPC / 4;
    if (i < n4) {
        const float4* p = (const float4*)g_part;
        float4 s = p[i];
#pragma unroll
        for (int z = 1; z < KSPLIT; z++) {
            float4 v = p[(size_t)z * n4 + i];
            s.x += v.x; s.y += v.y; s.z += v.z; s.w += v.w;
        }
        ((float4*)g_xp)[i] = s;
    }
}

// =====================================================================
// GEMM2 (tensor): g_dt[row][d] = softplus(sum_r xp[row][r]*dtw[d][r]+b[d])
// grid (8 Mtiles of 128, 32 Ntiles of 128), 256 thr (8 warps: 4M x 2N).
// K=128 = 8 chunks of 16, double-buffered. bf16 3-term split.
// =====================================================================
__global__ __launch_bounds__(256, 1)
void gemm2_kernel(const float* __restrict__ dtw, const float* __restrict__ dtb)
{
    __shared__ __nv_bfloat16 Ahi[2][128][LDK], Alo[2][128][LDK];
    __shared__ __nv_bfloat16 Bhi[2][128][LDK], Blo[2][128][LDK];

    const int tid = threadIdx.x;
    const int m0 = blockIdx.x * 128;
    const int n0 = blockIdx.y * 128;

    const int lane = tid & 31, wid = tid >> 5;
    const int wm = (wid >> 1) * 32;       // 0..96
    const int wn = (wid & 1) * 64;        // 0,64
    const int g = lane >> 2, t2 = (lane & 3) * 2;

    const int lrow = tid >> 1;            // 0..127
    const int lk = (tid & 1) * 8;         // 0 or 8

    const float* Ag = g_xp + (size_t)(m0 + lrow) * XPC + lk;
    const float* Bg = dtw + (size_t)(n0 + lrow) * DT_RANK + lk;

    float acc[2][8][4];
#pragma unroll
    for (int i = 0; i < 2; i++)
#pragma unroll
        for (int j = 0; j < 8; j++)
#pragma unroll
            for (int v = 0; v < 4; v++) acc[i][j][v] = 0.0f;

    float4 pa0, pa1, pb0, pb1;
    auto ldregs = [&](int c) {
        const int ko = c * 16;
        pa0 = *(const float4*)(Ag + ko);
        pa1 = *(const float4*)(Ag + ko + 4);
        pb0 = *(const float4*)(Bg + ko);
        pb1 = *(const float4*)(Bg + ko + 4);
    };
    auto stregs = [&](int buf) {
        uint32_t h0, l0, h1, l1;
        split2(pa0.x, pa0.y, h0, l0); split2(pa0.z, pa0.w, h1, l1);
        *(uint32_t*)&Ahi[buf][lrow][lk] = h0;     *(uint32_t*)&Ahi[buf][lrow][lk + 2] = h1;
        *(uint32_t*)&Alo[buf][lrow][lk] = l0;     *(uint32_t*)&Alo[buf][lrow][lk + 2] = l1;
        split2(pa1.x, pa1.y, h0, l0); split2(pa1.z, pa1.w, h1, l1);
        *(uint32_t*)&Ahi[buf][lrow][lk + 4] = h0; *(uint32_t*)&Ahi[buf][lrow][lk + 6] = h1;
        *(uint32_t*)&Alo[buf][lrow][lk + 4] = l0; *(uint32_t*)&Alo[buf][lrow][lk + 6] = l1;
        split2(pb0.x, pb0.y, h0, l0); split2(pb0.z, pb0.w, h1, l1);
        *(uint32_t*)&Bhi[buf][lrow][lk] = h0;     *(uint32_t*)&Bhi[buf][lrow][lk + 2] = h1;
        *(uint32_t*)&Blo[buf][lrow][lk] = l0;     *(uint32_t*)&Blo[buf][lrow][lk + 2] = l1;
        split2(pb1.x, pb1.y, h0, l0); split2(pb1.z, pb1.w, h1, l1);
        *(uint32_t*)&Bhi[buf][lrow][lk + 4] = h0; *(uint32_t*)&Bhi[buf][lrow][lk + 6] = h1;
        *(uint32_t*)&Blo[buf][lrow][lk + 4] = l0; *(uint32_t*)&Blo[buf][lrow][lk + 6] = l1;
    };

    ldregs(0);
    stregs(0);

    for (int c = 0; c < 8; c++) {
        __syncthreads();
        const int buf = c & 1;
        if (c + 1 < 8) ldregs(c + 1);

        uint32_t ah[2][4], al[2][4];
#pragma unroll
        for (int mt = 0; mt < 2; mt++) {
            const int r = wm + mt * 16 + g;
            ah[mt][0] = ldu(&Ahi[buf][r][t2]);      ah[mt][1] = ldu(&Ahi[buf][r + 8][t2]);
            ah[mt][2] = ldu(&Ahi[buf][r][t2 + 8]);  ah[mt][3] = ldu(&Ahi[buf][r + 8][t2 + 8]);
            al[mt][0] = ldu(&Alo[buf][r][t2]);      al[mt][1] = ldu(&Alo[buf][r + 8][t2]);
            al[mt][2] = ldu(&Alo[buf][r][t2 + 8]);  al[mt][3] = ldu(&Alo[buf][r + 8][t2 + 8]);
        }
#pragma unroll
        for (int nt = 0; nt < 8; nt++) {
            const int n = wn + nt * 8 + g;
            uint32_t bh0 = ldu(&Bhi[buf][n][t2]), bh1 = ldu(&Bhi[buf][n][t2 + 8]);
            uint32_t bl0 = ldu(&Blo[buf][n][t2]), bl1 = ldu(&Blo[buf][n][t2 + 8]);
#pragma unroll
            for (int mt = 0; mt < 2; mt++) {
                mma16816(acc[mt][nt], ah[mt][0], ah[mt][1], ah[mt][2], ah[mt][3], bh0, bh1);
                mma16816(acc[mt][nt], ah[mt][0], ah[mt][1], ah[mt][2], ah[mt][3], bl0, bl1);
                mma16816(acc[mt][nt], al[mt][0], al[mt][1], al[mt][2], al[mt][3], bh0, bh1);
            }
        }
        if (c + 1 < 8) stregs((c + 1) & 1);
    }

    // epilogue: softplus + bias -> g_dt
#pragma unroll
    for (int mt = 0; mt < 2; mt++) {
        const int r = m0 + wm + mt * 16 + g;
#pragma unroll
        for (int nt = 0; nt < 8; nt++) {
            const int col = n0 + wn + nt * 8 + t2;
            const float b0 = dtb[col], b1 = dtb[col + 1];
            *(float2*)&g_dt[(size_t)r * D_INNER + col] =
                make_float2(softplusf(acc[mt][nt][0] + b0), softplusf(acc[mt][nt][1] + b1));
            *(float2*)&g_dt[(size_t)(r + 8) * D_INNER + col] =
                make_float2(softplusf(acc[mt][nt][2] + b0), softplusf(acc[mt][nt][3] + b1));
        }
    }
}

// =====================================================================
// Scan: 256 blocks (2 batches x 128 d-tiles of 32 channels), 128 thr,
// 4 lanes/channel, 4 states/lane, cp.async double-buffered.
// =====================================================================
#define LT 64
#define NTILES (SEQLEN / LT)

__global__ __launch_bounds__(128, 4)
void scan_kernel(const float* __restrict__ x, const float* __restrict__ A_log,
                 const float* __restrict__ Dp, float* __restrict__ y)
{
    extern __shared__ float sm[];
    float* xs  = sm;                   // [2][LT][32]
    float* dts = xs + 2 * LT * 32;     // [2][LT][32]
    float* Bsm = dts + 2 * LT * 32;    // [2][LT][16]
    float* Csm = Bsm + 2 * LT * 16;    // [2][LT][16]

    const int tid = threadIdx.x;
    const int b   = blockIdx.x >> 7;
    const int d0  = (blockIdx.x & 127) * 32;
    const int lane = tid & 31;
    const int w    = tid >> 5;
    const int q    = lane & 3;
    const int cl   = w * 8 + (lane >> 2);
    const int d    = d0 + cl;

    float A2[4];
#pragma unroll
    for (int j = 0; j < 4; j++)
        A2[j] = -__expf(A_log[d * D_STATE + q * 4 + j]) * 1.4426950408889634f;
    const float Dd = Dp[d];

    float h0 = 0.f, h1 = 0.f, h2 = 0.f, h3 = 0.f;

    const float* xg  = x    + (size_t)b * SEQLEN * D_INNER + d0;
    const float* dtg = g_dt + (size_t)b * SEQLEN * D_INNER + d0;
    const float* Bg  = g_xp + (size_t)b * SEQLEN * XPC + DT_RANK;
    const float* Cg  = g_xp + (size_t)b * SEQLEN * XPC + DT_RANK + D_STATE;

    auto load_tile = [&](int t, int buf) {
        const int l0 = t * LT;
        for (int i = tid; i < LT * 8; i += 128) {
            int ll = i >> 3, sg = (i & 7) * 4;
            cp16(&xs [(buf * LT + ll) * 32 + sg], xg  + (size_t)(l0 + ll) * D_INNER + sg);
            cp16(&dts[(buf * LT + ll) * 32 + sg], dtg + (size_t)(l0 + ll) * D_INNER + sg);
        }
        for (int i = tid; i < LT * 4; i += 128) {
            int ll = i >> 2, sg = (i & 3) * 4;
            cp16(&Bsm[(buf * LT + ll) * 16 + sg], Bg + (size_t)(l0 + ll) * XPC + sg);
            cp16(&Csm[(buf * LT + ll) * 16 + sg], Cg + (size_t)(l0 + ll) * XPC + sg);
        }
    };

    load_tile(0, 0);
    cp_commit();

    for (int t = 0; t < NTILES; t++) {
        if (t + 1 < NTILES) {
            load_tile(t + 1, (t + 1) & 1);
            cp_commit();
            cp_wait<1>();
        } else {
            cp_wait<0>();
        }
        __syncthreads();

        const int buf = t & 1;
        const float* xsb  = &xs [buf * LT * 32];
        const float* dtb_ = &dts[buf * LT * 32];
        const float* Bb   = &Bsm[buf * LT * 16];
        const float* Cb   = &Csm[buf * LT * 16];

        float* yout = y + ((size_t)b * SEQLEN + t * LT) * D_INNER + d;

#pragma unroll 4
        for (int ll = 0; ll < LT; ll++) {
            float dtv = dtb_[ll * 32 + cl];
            float xv  = xsb [ll * 32 + cl];
            float4 Bv = *(const float4*)&Bb[ll * 16 + q * 4];
            float4 Cv = *(const float4*)&Cb[ll * 16 + q * 4];

            float dtx = dtv * xv;
            float e0 = ex2f(dtv * A2[0]);
            float e1 = ex2f(dtv * A2[1]);
            float e2 = ex2f(dtv * A2[2]);
            float e3 = ex2f(dtv * A2[3]);
            h0 = fmaf(e0, h0, dtx * Bv.x);
            h1 = fmaf(e1, h1, dtx * Bv.y);
            h2 = fmaf(e2, h2, dtx * Bv.z);
            h3 = fmaf(e3, h3, dtx * Bv.w);

            float p = h0 * Cv.x;
            p = fmaf(h1, Cv.y, p);
            p = fmaf(h2, Cv.z, p);
            p = fmaf(h3, Cv.w, p);
            p += __shfl_xor_sync(0xffffffffu, p, 1);
            p += __shfl_xor_sync(0xffffffffu, p, 2);

            if (q == 0) yout[(size_t)ll * D_INNER] = fmaf(Dd, xv, p);
        }
        __syncthreads();
    }
}

// =====================================================================
// launch
// =====================================================================
extern "C" void kernel_launch(void* const* d_in, const int* in_sizes, int n_in,
                              void* d_out, int out_size)
{
    const float* x     = (const float*)d_in[0];  // (2,512,4096)
    const float* A_log = (const float*)d_in[1];  // (4096,16)
    const float* Dp    = (const float*)d_in[2];  // (4096,)
    const float* xpw   = (const float*)d_in[3];  // (160,4096)
    const float* dtw   = (const float*)d_in[4];  // (4096,128)
    const float* dtb   = (const float*)d_in[5];  // (4096,)
    float* y = (float*)d_out;                    // (2,512,4096)

    gemm1_kernel<<<dim3(16, KSPLIT), 256>>>(x, xpw);
    reduce_kernel<<<(NROWS * XPC / 4 + 255) / 256, 256>>>();
    gemm2_kernel<<<dim3(8, 32), 256>>>(dtw, dtb);
    scan_kernel<<<256, 128, 49152>>>(x, A_log, Dp, y);
}